// round 1
// baseline (speedup 1.0000x reference)
#include <cuda_runtime.h>
#include <cuda_fp16.h>

#define BATCH 4
#define N 4096
#define RN (BATCH * N)          // 16384 rows (and 16384 batched columns)
#define EPS 1e-6f
#define NITER 20
#define SPLITS 32               // i-splits for column reduction

// Scratch (device globals: allowed; no cudaMalloc)
__device__ __half g_E[(size_t)BATCH * N * N];   // 128 MB: exp(x - rowmax) in fp16
__device__ float  g_r[RN];                      // per-row scalars
__device__ float  g_c[RN];                      // per-(batch,col) scalars
__device__ float  g_rowmax[RN];
__device__ float  g_vpart[SPLITS * RN];         // deterministic col partials (2 MB)

__device__ __forceinline__ float warpSum(float v) {
    #pragma unroll
    for (int o = 16; o > 0; o >>= 1) v += __shfl_xor_sync(0xffffffffu, v, o);
    return v;
}
__device__ __forceinline__ float warpMax(float v) {
    #pragma unroll
    for (int o = 16; o > 0; o >>= 1) v = fmaxf(v, __shfl_xor_sync(0xffffffffu, v, o));
    return v;
}

// ---------------------------------------------------------------------------
// prep: per-row max, E = exp(x - max) stored fp16, init r = c = 1
// one block (256 threads) per row; 16 elems/thread held in registers
// ---------------------------------------------------------------------------
__global__ __launch_bounds__(256) void prep_kernel(const float* __restrict__ logits) {
    const int row = blockIdx.x;
    const int t   = threadIdx.x;
    const float4* src = (const float4*)(logits + (size_t)row * N);

    float4 vals[4];
    #pragma unroll
    for (int k = 0; k < 4; ++k) vals[k] = src[t + k * 256];

    float m = -__int_as_float(0x7f800000);  // -inf
    #pragma unroll
    for (int k = 0; k < 4; ++k) {
        m = fmaxf(m, fmaxf(fmaxf(vals[k].x, vals[k].y), fmaxf(vals[k].z, vals[k].w)));
    }
    // block-reduce max
    __shared__ float sh[32];
    __shared__ float s_max;
    float wm = warpMax(m);
    int lane = t & 31, w = t >> 5;
    if (lane == 0) sh[w] = wm;
    __syncthreads();
    if (w == 0) {
        float v = (lane < 8) ? sh[lane] : -__int_as_float(0x7f800000);
        v = warpMax(v);
        if (lane == 0) s_max = v;
    }
    __syncthreads();
    const float mx = s_max;

    __half2* dst = (__half2*)(g_E + (size_t)row * N);
    #pragma unroll
    for (int k = 0; k < 4; ++k) {
        const float4 v = vals[k];
        const int i4 = t + k * 256;
        dst[2 * i4 + 0] = __floats2half2_rn(__expf(v.x - mx), __expf(v.y - mx));
        dst[2 * i4 + 1] = __floats2half2_rn(__expf(v.z - mx), __expf(v.w - mx));
    }
    if (t == 0) {
        g_rowmax[row] = mx;
        g_r[row] = 1.0f;
        g_c[row] = 1.0f;
    }
}

// ---------------------------------------------------------------------------
// row step: u_i = sum_j E_ij * c_j ; r_i <- r_i / (r_i*u_i + eps)
// one block (256 threads) per row
// ---------------------------------------------------------------------------
__global__ __launch_bounds__(256) void row_kernel() {
    const int row = blockIdx.x;
    const int b   = row >> 12;
    const int t   = threadIdx.x;
    const __half2* E2 = (const __half2*)g_E + (size_t)row * (N / 2);
    const float2*  c2 = (const float2*)(g_c + b * N);

    float acc = 0.0f;
    #pragma unroll
    for (int k = 0; k < 8; ++k) {
        const int j2 = t + k * 256;
        const float2 e = __half22float2(E2[j2]);
        const float2 c = c2[j2];
        acc = fmaf(e.x, c.x, acc);
        acc = fmaf(e.y, c.y, acc);
    }
    __shared__ float sh[32];
    float ws = warpSum(acc);
    int lane = t & 31, w = t >> 5;
    if (lane == 0) sh[w] = ws;
    __syncthreads();
    if (t == 0) {
        float u = 0.0f;
        #pragma unroll
        for (int i = 0; i < 8; ++i) u += sh[i];
        const float r = g_r[row];
        g_r[row] = r / (fmaf(r, u, EPS));
    }
}

// ---------------------------------------------------------------------------
// col step part 1: partial v_j = sum_{i in split} E_ij * r_i
// grid: BATCH * (N/256 jtiles) * SPLITS blocks, 128 threads (half2 per thread)
// deterministic: each block writes its own partial slot (no atomics)
// ---------------------------------------------------------------------------
__global__ __launch_bounds__(128) void col_kernel() {
    const int blk = blockIdx.x;
    const int jt  = blk & 15;          // 16 j-tiles of 256 cols
    const int s   = (blk >> 4) & (SPLITS - 1);
    const int b   = blk >> 9;          // / (16*32)
    const int t   = threadIdx.x;
    const int j2  = jt * 128 + t;      // half2 column index, 0..2047

    const __half2* E2 = (const __half2*)g_E + (size_t)b * N * (N / 2);
    const float*   rr = g_r + b * N;

    float ax = 0.0f, ay = 0.0f;
    const int i0 = s * (N / SPLITS);   // 128 rows per split
    #pragma unroll 4
    for (int i = i0; i < i0 + N / SPLITS; ++i) {
        const float2 e = __half22float2(E2[(size_t)i * (N / 2) + j2]);
        const float ri = rr[i];
        ax = fmaf(e.x, ri, ax);
        ay = fmaf(e.y, ri, ay);
    }
    float2* vp = (float2*)(g_vpart + s * RN + b * N);
    vp[j2] = make_float2(ax, ay);
}

// ---------------------------------------------------------------------------
// col step part 2: v_j = sum_s partial ; c_j <- c_j / (c_j*v_j + eps)
// fixed summation order -> deterministic
// ---------------------------------------------------------------------------
__global__ __launch_bounds__(256) void col_finalize() {
    const int j = blockIdx.x * 256 + threadIdx.x;   // 0..RN-1
    float v = 0.0f;
    #pragma unroll
    for (int s = 0; s < SPLITS; ++s) v += g_vpart[s * RN + j];
    const float c = g_c[j];
    g_c[j] = c / (fmaf(c, v, EPS));
}

// ---------------------------------------------------------------------------
// output: out_ij = exp(x_ij - rowmax_i) * r_i * c_j  (fp32 path for accuracy)
// ---------------------------------------------------------------------------
__global__ __launch_bounds__(256) void out_kernel(const float* __restrict__ logits,
                                                  float* __restrict__ out) {
    const size_t g  = (size_t)blockIdx.x * 256 + threadIdx.x;  // float4 index
    const size_t e0 = g * 4;
    const int row = (int)(e0 >> 12);
    const int b   = row >> 12;
    const int j   = (int)(e0 & (N - 1));

    const float mx = g_rowmax[row];
    const float r  = g_r[row];
    const float4 x = ((const float4*)logits)[g];
    const float4 c = *(const float4*)(g_c + b * N + j);

    float4 o;
    o.x = __expf(x.x - mx) * r * c.x;
    o.y = __expf(x.y - mx) * r * c.y;
    o.z = __expf(x.z - mx) * r * c.z;
    o.w = __expf(x.w - mx) * r * c.w;
    ((float4*)out)[g] = o;
}

extern "C" void kernel_launch(void* const* d_in, const int* in_sizes, int n_in,
                              void* d_out, int out_size) {
    const float* logits = (const float*)d_in[0];
    float* out = (float*)d_out;

    prep_kernel<<<RN, 256>>>(logits);
    for (int it = 0; it < NITER; ++it) {
        row_kernel<<<RN, 256>>>();
        col_kernel<<<BATCH * 16 * SPLITS, 128>>>();
        col_finalize<<<RN / 256, 256>>>();
    }
    const int out_blocks = (int)(((size_t)BATCH * N * N / 4) / 256);  // 65536
    out_kernel<<<out_blocks, 256>>>(logits, out);
}